// round 3
// baseline (speedup 1.0000x reference)
#include <cuda_runtime.h>
#include <cuda_bf16.h>
#include <cstdint>

// ============================================================================
// Problem constants
// ============================================================================
#define B_ROWS 8192

// Layer dims (real), padded dims: Npad multiple of 256, Kpad multiple of 64
// L1: 132(pad192) -> 2112 (pad2304)
// L2: 2112 -> 4224 (pad4352)
// L3: 4224 -> 8448 (pad8448)
// L4: 8448 -> 4224 (pad4352)
// L5: 4224 -> 64   (pad256)

#define MT 128
#define NT 256
#define KC 64
#define GEMM_THREADS 256

// SMEM stage layout (bytes)
#define STG_A_HI 0
#define STG_A_LO 16384
#define STG_W_HI 32768
#define STG_W_LO 65536
#define STAGE_BYTES 98304          // 96 KB
#define SMEM_TOTAL (2 * STAGE_BYTES)  // 192 KB

// ============================================================================
// Scratch (__device__ globals; no cudaMalloc allowed)
// ============================================================================
__device__ __nv_bfloat16 g_xHi[B_ROWS * 192];
__device__ __nv_bfloat16 g_xLo[B_ROWS * 192];

__device__ __nv_bfloat16 g_w1Hi[2304 * 192],   g_w1Lo[2304 * 192];
__device__ __nv_bfloat16 g_w2Hi[4352 * 2112],  g_w2Lo[4352 * 2112];
__device__ __nv_bfloat16 g_w3Hi[(size_t)8448 * 4224], g_w3Lo[(size_t)8448 * 4224];
__device__ __nv_bfloat16 g_w4Hi[(size_t)4352 * 8448], g_w4Lo[(size_t)4352 * 8448];
__device__ __nv_bfloat16 g_w5Hi[256 * 4224],   g_w5Lo[256 * 4224];

// Activation ping-pong (hi/lo pairs). A holds up to 8448 cols, B up to 4224.
__device__ __nv_bfloat16 g_actAHi[(size_t)B_ROWS * 8448], g_actALo[(size_t)B_ROWS * 8448];
__device__ __nv_bfloat16 g_actBHi[(size_t)B_ROWS * 4224], g_actBLo[(size_t)B_ROWS * 4224];

// ============================================================================
// PTX helpers
// ============================================================================
__device__ __forceinline__ uint32_t smem_u32(const void* p) {
    uint32_t a;
    asm("{ .reg .u64 t; cvta.to.shared.u64 t, %1; cvt.u32.u64 %0, t; }"
        : "=r"(a) : "l"(p));
    return a;
}

#define CP_ASYNC16(dst, src) \
    asm volatile("cp.async.cg.shared.global [%0], [%1], 16;" :: "r"(dst), "l"(src))

#define CP_COMMIT() asm volatile("cp.async.commit_group;" ::: "memory")
#define CP_WAIT(n)  asm volatile("cp.async.wait_group %0;" :: "n"(n) : "memory")

#define LDSM4(r, addr) \
    asm volatile("ldmatrix.sync.aligned.m8n8.x4.shared.b16 {%0,%1,%2,%3}, [%4];" \
                 : "=r"((r)[0]), "=r"((r)[1]), "=r"((r)[2]), "=r"((r)[3]) : "r"(addr))

#define MMA16816(d, a, b0, b1) \
    asm volatile("mma.sync.aligned.m16n8k16.row.col.f32.bf16.bf16.f32 " \
                 "{%0,%1,%2,%3},{%4,%5,%6,%7},{%8,%9},{%0,%1,%2,%3};" \
                 : "+f"((d)[0]), "+f"((d)[1]), "+f"((d)[2]), "+f"((d)[3]) \
                 : "r"((a)[0]), "r"((a)[1]), "r"((a)[2]), "r"((a)[3]), \
                   "r"(b0), "r"(b1))

// swizzled byte offset within a tile: row r (128B rows), 16B-chunk c (0..7)
__device__ __forceinline__ uint32_t swz(int r, int c) {
    return (uint32_t)(r * 128 + ((c ^ (r & 7)) << 4));
}

// ============================================================================
// GEMM: out[8192, Nreal] = act(A @ W^T + bias), bf16x3 split precision.
// A: hi/lo bf16 [8192, Kpad] (stride Kpad). W: hi/lo bf16 [Npad, Kpad] zero-padded.
// Outputs: oHi/oLo bf16 [8192, Nreal] (if oF==nullptr), else oF fp32 [8192, Nreal].
// ============================================================================
__global__ void __launch_bounds__(GEMM_THREADS, 1)
gemm_bf16x3(const __nv_bfloat16* __restrict__ aHi, const __nv_bfloat16* __restrict__ aLo,
            const __nv_bfloat16* __restrict__ wHi, const __nv_bfloat16* __restrict__ wLo,
            const float* __restrict__ bias,
            __nv_bfloat16* __restrict__ oHi, __nv_bfloat16* __restrict__ oLo,
            float* __restrict__ oF,
            int Nreal, int Kpad, int doRelu)
{
    extern __shared__ char smem[];
    const uint32_t sb = smem_u32(smem);
    const int tid  = threadIdx.x;
    const int wid  = tid >> 5;
    const int lane = tid & 31;
    const int m0 = blockIdx.y * MT;
    const int n0 = blockIdx.x * NT;
    const int nChunks = Kpad / KC;

    // ---------------- async tile loader ------------------------------------
    auto load_chunk = [&](int c, int stage) {
        const uint32_t base = sb + stage * STAGE_BYTES;
        const int k0 = c * KC;
        #pragma unroll
        for (int i = 0; i < 4; i++) {                    // A: 1024 x 16B
            int j = tid + i * GEMM_THREADS;
            int r = j >> 3, cc = j & 7;
            uint32_t d = base + swz(r, cc);
            size_t so = (size_t)(m0 + r) * Kpad + k0 + cc * 8;
            CP_ASYNC16(d + STG_A_HI, aHi + so);
            CP_ASYNC16(d + STG_A_LO, aLo + so);
        }
        #pragma unroll
        for (int i = 0; i < 8; i++) {                    // W: 2048 x 16B
            int j = tid + i * GEMM_THREADS;
            int r = j >> 3, cc = j & 7;
            uint32_t d = base + swz(r, cc);
            size_t so = (size_t)(n0 + r) * Kpad + k0 + cc * 8;
            CP_ASYNC16(d + STG_W_HI, wHi + so);
            CP_ASYNC16(d + STG_W_LO, wLo + so);
        }
    };

    float acc[4][8][4];
    #pragma unroll
    for (int t = 0; t < 4; t++)
        #pragma unroll
        for (int nf = 0; nf < 8; nf++)
            #pragma unroll
            for (int e = 0; e < 4; e++) acc[t][nf][e] = 0.0f;

    const int mBase = (wid & 1) * 64;     // warp M offset in tile
    const int nBase = (wid >> 1) * 64;    // warp N offset in tile

    load_chunk(0, 0);
    CP_COMMIT();

    for (int c = 0; c < nChunks; c++) {
        if (c + 1 < nChunks) {
            load_chunk(c + 1, (c + 1) & 1);
            CP_COMMIT();
            CP_WAIT(1);
        } else {
            CP_WAIT(0);
        }
        __syncthreads();

        const uint32_t base = sb + (c & 1) * STAGE_BYTES;
        #pragma unroll
        for (int s = 0; s < 4; s++) {                 // 4 x k16 per chunk
            // A fragments (hi & lo): 4 m-tiles of 16
            uint32_t aH[4][4], aL[4][4];
            #pragma unroll
            for (int t = 0; t < 4; t++) {
                int row = mBase + t * 16 + (lane & 15);
                int c16 = s * 2 + (lane >> 4);
                uint32_t ad = base + swz(row, c16);
                LDSM4(aH[t], ad + STG_A_HI);
                LDSM4(aL[t], ad + STG_A_LO);
            }
            #pragma unroll
            for (int p = 0; p < 4; p++) {             // 4 n-pairs of 16
                int g = lane >> 3;
                int row = nBase + p * 16 + (lane & 7) + ((g >> 1) << 3);
                int c16 = s * 2 + (g & 1);
                uint32_t wd = base + swz(row, c16);
                uint32_t bH[4], bL[4];
                LDSM4(bH, wd + STG_W_HI);
                LDSM4(bL, wd + STG_W_LO);
                #pragma unroll
                for (int t = 0; t < 4; t++) {
                    MMA16816(acc[t][2 * p],     aH[t], bH[0], bH[1]);
                    MMA16816(acc[t][2 * p],     aL[t], bH[0], bH[1]);
                    MMA16816(acc[t][2 * p],     aH[t], bL[0], bL[1]);
                    MMA16816(acc[t][2 * p + 1], aH[t], bH[2], bH[3]);
                    MMA16816(acc[t][2 * p + 1], aL[t], bH[2], bH[3]);
                    MMA16816(acc[t][2 * p + 1], aH[t], bL[2], bL[3]);
                }
            }
        }
        __syncthreads();
    }

    // ---------------- epilogue ---------------------------------------------
    const int mW = m0 + mBase;
    const int nW = n0 + nBase;
    #pragma unroll
    for (int t = 0; t < 4; t++) {
        #pragma unroll
        for (int nf = 0; nf < 8; nf++) {
            int cc = nW + nf * 8 + ((lane & 3) << 1);
            if (cc >= Nreal) continue;
            int r0 = mW + t * 16 + (lane >> 2);
            int r1 = r0 + 8;
            float bv0 = bias[cc], bv1 = bias[cc + 1];
            float v00 = acc[t][nf][0] + bv0;
            float v01 = acc[t][nf][1] + bv1;
            float v10 = acc[t][nf][2] + bv0;
            float v11 = acc[t][nf][3] + bv1;
            if (doRelu) {
                v00 = fmaxf(v00, 0.f); v01 = fmaxf(v01, 0.f);
                v10 = fmaxf(v10, 0.f); v11 = fmaxf(v11, 0.f);
            }
            if (oF) {
                *reinterpret_cast<float2*>(oF + (size_t)r0 * Nreal + cc) = make_float2(v00, v01);
                *reinterpret_cast<float2*>(oF + (size_t)r1 * Nreal + cc) = make_float2(v10, v11);
            } else {
                __nv_bfloat16 h00 = __float2bfloat16(v00), h01 = __float2bfloat16(v01);
                __nv_bfloat16 h10 = __float2bfloat16(v10), h11 = __float2bfloat16(v11);
                __nv_bfloat16 l00 = __float2bfloat16(v00 - __bfloat162float(h00));
                __nv_bfloat16 l01 = __float2bfloat16(v01 - __bfloat162float(h01));
                __nv_bfloat16 l10 = __float2bfloat16(v10 - __bfloat162float(h10));
                __nv_bfloat16 l11 = __float2bfloat16(v11 - __bfloat162float(h11));
                *reinterpret_cast<__nv_bfloat162*>(oHi + (size_t)r0 * Nreal + cc) = __nv_bfloat162(h00, h01);
                *reinterpret_cast<__nv_bfloat162*>(oHi + (size_t)r1 * Nreal + cc) = __nv_bfloat162(h10, h11);
                *reinterpret_cast<__nv_bfloat162*>(oLo + (size_t)r0 * Nreal + cc) = __nv_bfloat162(l00, l01);
                *reinterpret_cast<__nv_bfloat162*>(oLo + (size_t)r1 * Nreal + cc) = __nv_bfloat162(l10, l11);
            }
        }
    }
}

// ============================================================================
// prepack: W fp32 [N,K] -> hi/lo bf16 [Npad,Kpad], zero-padded
// ============================================================================
__global__ void split_pad_kernel(const float* __restrict__ W,
                                 __nv_bfloat16* __restrict__ hi,
                                 __nv_bfloat16* __restrict__ lo,
                                 int N, int K, int Kpad, int total)
{
    int idx = blockIdx.x * blockDim.x + threadIdx.x;
    if (idx >= total) return;
    int n = idx / Kpad, k = idx - n * Kpad;
    float v = (n < N && k < K) ? W[(size_t)n * K + k] : 0.0f;
    __nv_bfloat16 h = __float2bfloat16(v);
    hi[idx] = h;
    lo[idx] = __float2bfloat16(v - __bfloat162float(h));
}

// concat + split: x = [state(128) | pref(4) | zeros(60)] -> hi/lo [8192,192]
__global__ void concat_split_kernel(const float* __restrict__ state,
                                    const float* __restrict__ pref,
                                    __nv_bfloat16* __restrict__ hi,
                                    __nv_bfloat16* __restrict__ lo)
{
    int idx = blockIdx.x * blockDim.x + threadIdx.x;
    if (idx >= B_ROWS * 192) return;
    int b = idx / 192, c = idx - b * 192;
    float v = 0.0f;
    if (c < 128)      v = state[b * 128 + c];
    else if (c < 132) v = pref[b * 4 + (c - 128)];
    __nv_bfloat16 h = __float2bfloat16(v);
    hi[idx] = h;
    lo[idx] = __float2bfloat16(v - __bfloat162float(h));
}

// ============================================================================
// envelope: a* = argmax_a <q[b,a,:], pref[b,:]> (first-tie), hq = q[b,a*,:]
// ============================================================================
__global__ void envelope_kernel(const float* __restrict__ q,
                                const float* __restrict__ pref,
                                float* __restrict__ hq)
{
    int b = blockIdx.x * blockDim.x + threadIdx.x;
    if (b >= B_ROWS) return;
    float p0 = pref[b * 4 + 0], p1 = pref[b * 4 + 1];
    float p2 = pref[b * 4 + 2], p3 = pref[b * 4 + 3];
    const float* qb = q + (size_t)b * 64;
    float best = -3.402823466e+38f;
    int ba = 0;
    #pragma unroll
    for (int a = 0; a < 16; a++) {
        float ip = qb[a * 4 + 0] * p0 + qb[a * 4 + 1] * p1
                 + qb[a * 4 + 2] * p2 + qb[a * 4 + 3] * p3;
        if (ip > best) { best = ip; ba = a; }
    }
    hq[b * 4 + 0] = qb[ba * 4 + 0];
    hq[b * 4 + 1] = qb[ba * 4 + 1];
    hq[b * 4 + 2] = qb[ba * 4 + 2];
    hq[b * 4 + 3] = qb[ba * 4 + 3];
}

// ============================================================================
// launch
// ============================================================================
static inline void* sym(const void* s) { void* p; cudaGetSymbolAddress(&p, s); return p; }

extern "C" void kernel_launch(void* const* d_in, const int* in_sizes, int n_in,
                              void* d_out, int out_size)
{
    const float* state = (const float*)d_in[0];
    const float* pref  = (const float*)d_in[1];
    const float* w1 = (const float*)d_in[2];  const float* b1 = (const float*)d_in[3];
    const float* w2 = (const float*)d_in[4];  const float* b2 = (const float*)d_in[5];
    const float* w3 = (const float*)d_in[6];  const float* b3 = (const float*)d_in[7];
    const float* w4 = (const float*)d_in[8];  const float* b4 = (const float*)d_in[9];
    const float* wq = (const float*)d_in[10]; const float* bq = (const float*)d_in[11];

    float* out = (float*)d_out;
    float* hq = out;                       // [8192, 4]
    float* q  = out + (size_t)B_ROWS * 4;  // [8192, 64]

    __nv_bfloat16* xHi = (__nv_bfloat16*)sym(g_xHi);
    __nv_bfloat16* xLo = (__nv_bfloat16*)sym(g_xLo);
    __nv_bfloat16* w1Hi = (__nv_bfloat16*)sym(g_w1Hi); __nv_bfloat16* w1Lo = (__nv_bfloat16*)sym(g_w1Lo);
    __nv_bfloat16* w2Hi = (__nv_bfloat16*)sym(g_w2Hi); __nv_bfloat16* w2Lo = (__nv_bfloat16*)sym(g_w2Lo);
    __nv_bfloat16* w3Hi = (__nv_bfloat16*)sym(g_w3Hi); __nv_bfloat16* w3Lo = (__nv_bfloat16*)sym(g_w3Lo);
    __nv_bfloat16* w4Hi = (__nv_bfloat16*)sym(g_w4Hi); __nv_bfloat16* w4Lo = (__nv_bfloat16*)sym(g_w4Lo);
    __nv_bfloat16* w5Hi = (__nv_bfloat16*)sym(g_w5Hi); __nv_bfloat16* w5Lo = (__nv_bfloat16*)sym(g_w5Lo);
    __nv_bfloat16* aHi = (__nv_bfloat16*)sym(g_actAHi); __nv_bfloat16* aLo = (__nv_bfloat16*)sym(g_actALo);
    __nv_bfloat16* bHi = (__nv_bfloat16*)sym(g_actBHi); __nv_bfloat16* bLo = (__nv_bfloat16*)sym(g_actBLo);

    cudaFuncSetAttribute(gemm_bf16x3,
                         cudaFuncAttributeMaxDynamicSharedMemorySize, SMEM_TOTAL);

    // ---- prepack ----
    concat_split_kernel<<<(B_ROWS * 192 + 255) / 256, 256>>>(state, pref, xHi, xLo);
    {
        int t1 = 2304 * 192;
        split_pad_kernel<<<(t1 + 255) / 256, 256>>>(w1, w1Hi, w1Lo, 2112, 132, 192, t1);
        int t2 = 4352 * 2112;
        split_pad_kernel<<<(t2 + 255) / 256, 256>>>(w2, w2Hi, w2Lo, 4224, 2112, 2112, t2);
        int t3 = 8448 * 4224;
        split_pad_kernel<<<(t3 + 255) / 256, 256>>>(w3, w3Hi, w3Lo, 8448, 4224, 4224, t3);
        int t4 = 4352 * 8448;
        split_pad_kernel<<<(t4 + 255) / 256, 256>>>(w4, w4Hi, w4Lo, 4224, 8448, 8448, t4);
        int t5 = 256 * 4224;
        split_pad_kernel<<<(t5 + 255) / 256, 256>>>(wq, w5Hi, w5Lo, 64, 4224, 4224, t5);
    }

    // ---- layers ----
    dim3 blk(GEMM_THREADS);
    // L1: [8192,192] x [2304,192] -> act A (2112)
    gemm_bf16x3<<<dim3(2304 / NT, B_ROWS / MT), blk, SMEM_TOTAL>>>(
        xHi, xLo, w1Hi, w1Lo, b1, aHi, aLo, nullptr, 2112, 192, 1);
    // L2: [8192,2112] x [4352,2112] -> act B (4224)
    gemm_bf16x3<<<dim3(4352 / NT, B_ROWS / MT), blk, SMEM_TOTAL>>>(
        aHi, aLo, w2Hi, w2Lo, b2, bHi, bLo, nullptr, 4224, 2112, 1);
    // L3: [8192,4224] x [8448,4224] -> act A (8448)
    gemm_bf16x3<<<dim3(8448 / NT, B_ROWS / MT), blk, SMEM_TOTAL>>>(
        bHi, bLo, w3Hi, w3Lo, b3, aHi, aLo, nullptr, 8448, 4224, 1);
    // L4: [8192,8448] x [4352,8448] -> act B (4224)
    gemm_bf16x3<<<dim3(4352 / NT, B_ROWS / MT), blk, SMEM_TOTAL>>>(
        aHi, aLo, w4Hi, w4Lo, b4, bHi, bLo, nullptr, 4224, 8448, 1);
    // L5: [8192,4224] x [256,4224] -> q fp32 (64), no relu
    gemm_bf16x3<<<dim3(256 / NT, B_ROWS / MT), blk, SMEM_TOTAL>>>(
        bHi, bLo, w5Hi, w5Lo, bq, nullptr, nullptr, q, 64, 4224, 0);

    envelope_kernel<<<(B_ROWS + 255) / 256, 256>>>(q, pref, hq);
}

// round 5
// speedup vs baseline: 1.0145x; 1.0145x over previous
#include <cuda_runtime.h>
#include <cuda_bf16.h>
#include <cstdint>

// ============================================================================
// Problem constants
// ============================================================================
#define B_ROWS 8192

// L1: 132(pad192)  -> 2112 (pad2304)   bf16x3
// L2: 2112         -> 4224 (pad4352)   bf16x3
// L3: 4224         -> 8448             bf16x3
// L4: 8448         -> 4224 (pad4352)   bf16x3
// L5: 4224         -> 64   (pad256)    bf16x3

#define MT 128
#define NT 256
#define KC 64
#define GEMM_THREADS 256

#define STG_A_HI 0
#define STG_A_LO 16384
#define STG_W_HI 32768
#define STG_W_LO 65536
#define STAGE_BYTES 98304          // 96 KB
#define SMEM_TOTAL (2 * STAGE_BYTES)

// ============================================================================
// Scratch (__device__ globals; no cudaMalloc allowed)
// ============================================================================
__device__ __nv_bfloat16 g_xHi[B_ROWS * 192];
__device__ __nv_bfloat16 g_xLo[B_ROWS * 192];

__device__ __nv_bfloat16 g_w1Hi[2304 * 192],  g_w1Lo[2304 * 192];
__device__ __nv_bfloat16 g_w2Hi[(size_t)4352 * 2112], g_w2Lo[(size_t)4352 * 2112];
__device__ __nv_bfloat16 g_w3Hi[(size_t)8448 * 4224], g_w3Lo[(size_t)8448 * 4224];
__device__ __nv_bfloat16 g_w4Hi[(size_t)4352 * 8448], g_w4Lo[(size_t)4352 * 8448];
__device__ __nv_bfloat16 g_w5Hi[256 * 4224],  g_w5Lo[256 * 4224];

__device__ __nv_bfloat16 g_actAHi[(size_t)B_ROWS * 8448], g_actALo[(size_t)B_ROWS * 8448];
__device__ __nv_bfloat16 g_actBHi[(size_t)B_ROWS * 4224], g_actBLo[(size_t)B_ROWS * 4224];

// ============================================================================
// PTX helpers
// ============================================================================
__device__ __forceinline__ uint32_t smem_u32(const void* p) {
    uint32_t a;
    asm("{ .reg .u64 t; cvta.to.shared.u64 t, %1; cvt.u32.u64 %0, t; }"
        : "=r"(a) : "l"(p));
    return a;
}

#define CP_ASYNC16(dst, src) \
    asm volatile("cp.async.cg.shared.global [%0], [%1], 16;" :: "r"(dst), "l"(src))

#define CP_COMMIT() asm volatile("cp.async.commit_group;" ::: "memory")
#define CP_WAIT(n)  asm volatile("cp.async.wait_group %0;" :: "n"(n) : "memory")

#define LDSM4(r, addr) \
    asm volatile("ldmatrix.sync.aligned.m8n8.x4.shared.b16 {%0,%1,%2,%3}, [%4];" \
                 : "=r"((r)[0]), "=r"((r)[1]), "=r"((r)[2]), "=r"((r)[3]) : "r"(addr))

#define MMA_BF16(d, a, b0, b1) \
    asm volatile("mma.sync.aligned.m16n8k16.row.col.f32.bf16.bf16.f32 " \
                 "{%0,%1,%2,%3},{%4,%5,%6,%7},{%8,%9},{%0,%1,%2,%3};" \
                 : "+f"((d)[0]), "+f"((d)[1]), "+f"((d)[2]), "+f"((d)[3]) \
                 : "r"((a)[0]), "r"((a)[1]), "r"((a)[2]), "r"((a)[3]), \
                   "r"(b0), "r"(b1))

__device__ __forceinline__ uint32_t swz(int r, int c) {
    return (uint32_t)(r * 128 + ((c ^ (r & 7)) << 4));
}

// ============================================================================
// GEMM: out[8192, Nreal] = act(A @ W^T + bias), bf16x3 split precision.
// OUTFMT 0: bf16 hi/lo pair   2: fp32
// ============================================================================
template<int OUTFMT>
__global__ void __launch_bounds__(GEMM_THREADS, 1)
gemm_bf16x3(const __nv_bfloat16* __restrict__ aHi, const __nv_bfloat16* __restrict__ aLo,
            const __nv_bfloat16* __restrict__ wHi, const __nv_bfloat16* __restrict__ wLo,
            const float* __restrict__ bias,
            __nv_bfloat16* __restrict__ oHi, __nv_bfloat16* __restrict__ oLo,
            float* __restrict__ oF,
            int Nreal, int Kpad, int doRelu)
{
    extern __shared__ char smem[];
    const uint32_t sb = smem_u32(smem);
    const int tid  = threadIdx.x;
    const int wid  = tid >> 5;
    const int lane = tid & 31;
    const int m0 = blockIdx.y * MT;
    const int n0 = blockIdx.x * NT;
    const int nChunks = Kpad / KC;

    auto load_chunk = [&](int c, int stage) {
        const uint32_t base = sb + stage * STAGE_BYTES;
        const int k0 = c * KC;
        #pragma unroll
        for (int i = 0; i < 4; i++) {                    // A: 1024 x 16B
            int j = tid + i * GEMM_THREADS;
            int r = j >> 3, cc = j & 7;
            uint32_t d = base + swz(r, cc);
            size_t so = (size_t)(m0 + r) * Kpad + k0 + cc * 8;
            CP_ASYNC16(d + STG_A_HI, aHi + so);
            CP_ASYNC16(d + STG_A_LO, aLo + so);
        }
        #pragma unroll
        for (int i = 0; i < 8; i++) {                    // W: 2048 x 16B
            int j = tid + i * GEMM_THREADS;
            int r = j >> 3, cc = j & 7;
            uint32_t d = base + swz(r, cc);
            size_t so = (size_t)(n0 + r) * Kpad + k0 + cc * 8;
            CP_ASYNC16(d + STG_W_HI, wHi + so);
            CP_ASYNC16(d + STG_W_LO, wLo + so);
        }
    };

    float acc[4][8][4];
    #pragma unroll
    for (int t = 0; t < 4; t++)
        #pragma unroll
        for (int nf = 0; nf < 8; nf++)
            #pragma unroll
            for (int e = 0; e < 4; e++) acc[t][nf][e] = 0.0f;

    const int mBase = (wid & 1) * 64;
    const int nBase = (wid >> 1) * 64;

    load_chunk(0, 0);
    CP_COMMIT();

    for (int c = 0; c < nChunks; c++) {
        if (c + 1 < nChunks) {
            load_chunk(c + 1, (c + 1) & 1);
            CP_COMMIT();
            CP_WAIT(1);
        } else {
            CP_WAIT(0);
        }
        __syncthreads();

        const uint32_t base = sb + (c & 1) * STAGE_BYTES;
        #pragma unroll
        for (int s = 0; s < 4; s++) {
            uint32_t aH[4][4], aL[4][4];
            #pragma unroll
            for (int t = 0; t < 4; t++) {
                int row = mBase + t * 16 + (lane & 15);
                int c16 = s * 2 + (lane >> 4);
                uint32_t ad = base + swz(row, c16);
                LDSM4(aH[t], ad + STG_A_HI);
                LDSM4(aL[t], ad + STG_A_LO);
            }
            #pragma unroll
            for (int p = 0; p < 4; p++) {
                int g = lane >> 3;
                int row = nBase + p * 16 + (lane & 7) + ((g >> 1) << 3);
                int c16 = s * 2 + (g & 1);
                uint32_t wd = base + swz(row, c16);
                uint32_t bH[4], bL[4];
                LDSM4(bH, wd + STG_W_HI);
                LDSM4(bL, wd + STG_W_LO);
                // term-major ordering: same-accumulator MMAs are 8 apart
                #pragma unroll
                for (int t = 0; t < 4; t++) {
                    MMA_BF16(acc[t][2 * p],     aH[t], bH[0], bH[1]);
                    MMA_BF16(acc[t][2 * p + 1], aH[t], bH[2], bH[3]);
                }
                #pragma unroll
                for (int t = 0; t < 4; t++) {
                    MMA_BF16(acc[t][2 * p],     aL[t], bH[0], bH[1]);
                    MMA_BF16(acc[t][2 * p + 1], aL[t], bH[2], bH[3]);
                }
                #pragma unroll
                for (int t = 0; t < 4; t++) {
                    MMA_BF16(acc[t][2 * p],     aH[t], bL[0], bL[1]);
                    MMA_BF16(acc[t][2 * p + 1], aH[t], bL[2], bL[3]);
                }
            }
        }
        __syncthreads();
    }

    // ---------------- epilogue ---------------------------------------------
    const int mW = m0 + mBase;
    const int nW = n0 + nBase;
    #pragma unroll
    for (int t = 0; t < 4; t++) {
        #pragma unroll
        for (int nf = 0; nf < 8; nf++) {
            int cc = nW + nf * 8 + ((lane & 3) << 1);
            if (cc >= Nreal) continue;
            int r0 = mW + t * 16 + (lane >> 2);
            int r1 = r0 + 8;
            float bv0 = bias[cc], bv1 = bias[cc + 1];
            float v00 = acc[t][nf][0] + bv0;
            float v01 = acc[t][nf][1] + bv1;
            float v10 = acc[t][nf][2] + bv0;
            float v11 = acc[t][nf][3] + bv1;
            if (doRelu) {
                v00 = fmaxf(v00, 0.f); v01 = fmaxf(v01, 0.f);
                v10 = fmaxf(v10, 0.f); v11 = fmaxf(v11, 0.f);
            }
            if constexpr (OUTFMT == 2) {
                *reinterpret_cast<float2*>(oF + (size_t)r0 * Nreal + cc) = make_float2(v00, v01);
                *reinterpret_cast<float2*>(oF + (size_t)r1 * Nreal + cc) = make_float2(v10, v11);
            } else {
                __nv_bfloat16 h00 = __float2bfloat16(v00), h01 = __float2bfloat16(v01);
                __nv_bfloat16 h10 = __float2bfloat16(v10), h11 = __float2bfloat16(v11);
                __nv_bfloat16 l00 = __float2bfloat16(v00 - __bfloat162float(h00));
                __nv_bfloat16 l01 = __float2bfloat16(v01 - __bfloat162float(h01));
                __nv_bfloat16 l10 = __float2bfloat16(v10 - __bfloat162float(h10));
                __nv_bfloat16 l11 = __float2bfloat16(v11 - __bfloat162float(h11));
                *reinterpret_cast<__nv_bfloat162*>(oHi + (size_t)r0 * Nreal + cc) = __nv_bfloat162(h00, h01);
                *reinterpret_cast<__nv_bfloat162*>(oHi + (size_t)r1 * Nreal + cc) = __nv_bfloat162(h10, h11);
                *reinterpret_cast<__nv_bfloat162*>(oLo + (size_t)r0 * Nreal + cc) = __nv_bfloat162(l00, l01);
                *reinterpret_cast<__nv_bfloat162*>(oLo + (size_t)r1 * Nreal + cc) = __nv_bfloat162(l10, l11);
            }
        }
    }
}

// ============================================================================
// Prepack kernels
// ============================================================================
__global__ void split_pad_bf16(const float* __restrict__ W,
                               __nv_bfloat16* __restrict__ hi,
                               __nv_bfloat16* __restrict__ lo,
                               int N, int K, int Kpad, int total)
{
    int idx = blockIdx.x * blockDim.x + threadIdx.x;
    if (idx >= total) return;
    int n = idx / Kpad, k = idx - n * Kpad;
    float v = (n < N && k < K) ? W[(size_t)n * K + k] : 0.0f;
    __nv_bfloat16 h = __float2bfloat16(v);
    hi[idx] = h;
    lo[idx] = __float2bfloat16(v - __bfloat162float(h));
}

__global__ void pad_rows_bf16pair(const float* __restrict__ W,
                                  __nv_bfloat16* __restrict__ hi,
                                  __nv_bfloat16* __restrict__ lo,
                                  int N, int K)
{
    int n = blockIdx.x;
    const float4* src = reinterpret_cast<const float4*>(W + (size_t)n * K);
    uint2* dhi = reinterpret_cast<uint2*>(hi + (size_t)n * K);
    uint2* dlo = reinterpret_cast<uint2*>(lo + (size_t)n * K);
    int nv = K >> 2;
    bool valid = (n < N);
    for (int i = threadIdx.x; i < nv; i += blockDim.x) {
        float4 v = valid ? src[i] : make_float4(0.f, 0.f, 0.f, 0.f);
        __nv_bfloat16 h0 = __float2bfloat16(v.x), h1 = __float2bfloat16(v.y);
        __nv_bfloat16 h2 = __float2bfloat16(v.z), h3 = __float2bfloat16(v.w);
        uint2 uh, ul;
        uh.x = (uint32_t)__bfloat16_as_ushort(h0) | ((uint32_t)__bfloat16_as_ushort(h1) << 16);
        uh.y = (uint32_t)__bfloat16_as_ushort(h2) | ((uint32_t)__bfloat16_as_ushort(h3) << 16);
        __nv_bfloat16 l0 = __float2bfloat16(v.x - __bfloat162float(h0));
        __nv_bfloat16 l1 = __float2bfloat16(v.y - __bfloat162float(h1));
        __nv_bfloat16 l2 = __float2bfloat16(v.z - __bfloat162float(h2));
        __nv_bfloat16 l3 = __float2bfloat16(v.w - __bfloat162float(h3));
        ul.x = (uint32_t)__bfloat16_as_ushort(l0) | ((uint32_t)__bfloat16_as_ushort(l1) << 16);
        ul.y = (uint32_t)__bfloat16_as_ushort(l2) | ((uint32_t)__bfloat16_as_ushort(l3) << 16);
        dhi[i] = uh;
        dlo[i] = ul;
    }
}

__global__ void concat_split_kernel(const float* __restrict__ state,
                                    const float* __restrict__ pref,
                                    __nv_bfloat16* __restrict__ hi,
                                    __nv_bfloat16* __restrict__ lo)
{
    int idx = blockIdx.x * blockDim.x + threadIdx.x;
    if (idx >= B_ROWS * 192) return;
    int b = idx / 192, c = idx - b * 192;
    float v = 0.0f;
    if (c < 128)      v = state[b * 128 + c];
    else if (c < 132) v = pref[b * 4 + (c - 128)];
    __nv_bfloat16 h = __float2bfloat16(v);
    hi[idx] = h;
    lo[idx] = __float2bfloat16(v - __bfloat162float(h));
}

// ============================================================================
// envelope
// ============================================================================
__global__ void envelope_kernel(const float* __restrict__ q,
                                const float* __restrict__ pref,
                                float* __restrict__ hq)
{
    int b = blockIdx.x * blockDim.x + threadIdx.x;
    if (b >= B_ROWS) return;
    float p0 = pref[b * 4 + 0], p1 = pref[b * 4 + 1];
    float p2 = pref[b * 4 + 2], p3 = pref[b * 4 + 3];
    const float* qb = q + (size_t)b * 64;
    float best = -3.402823466e+38f;
    int ba = 0;
    #pragma unroll
    for (int a = 0; a < 16; a++) {
        float ip = qb[a * 4 + 0] * p0 + qb[a * 4 + 1] * p1
                 + qb[a * 4 + 2] * p2 + qb[a * 4 + 3] * p3;
        if (ip > best) { best = ip; ba = a; }
    }
    hq[b * 4 + 0] = qb[ba * 4 + 0];
    hq[b * 4 + 1] = qb[ba * 4 + 1];
    hq[b * 4 + 2] = qb[ba * 4 + 2];
    hq[b * 4 + 3] = qb[ba * 4 + 3];
}

// ============================================================================
// launch  — ordered so ncu (-s 5 -c 1) captures launch #6 = L2's GEMM
// ============================================================================
static inline void* sym(const void* s) { void* p; cudaGetSymbolAddress(&p, s); return p; }

extern "C" void kernel_launch(void* const* d_in, const int* in_sizes, int n_in,
                              void* d_out, int out_size)
{
    const float* state = (const float*)d_in[0];
    const float* pref  = (const float*)d_in[1];
    const float* w1 = (const float*)d_in[2];  const float* b1 = (const float*)d_in[3];
    const float* w2 = (const float*)d_in[4];  const float* b2 = (const float*)d_in[5];
    const float* w3 = (const float*)d_in[6];  const float* b3 = (const float*)d_in[7];
    const float* w4 = (const float*)d_in[8];  const float* b4 = (const float*)d_in[9];
    const float* wq = (const float*)d_in[10]; const float* bq = (const float*)d_in[11];

    float* out = (float*)d_out;
    float* hq = out;                       // [8192, 4]
    float* q  = out + (size_t)B_ROWS * 4;  // [8192, 64]

    __nv_bfloat16* xHi = (__nv_bfloat16*)sym(g_xHi);
    __nv_bfloat16* xLo = (__nv_bfloat16*)sym(g_xLo);
    __nv_bfloat16* w1Hi = (__nv_bfloat16*)sym(g_w1Hi); __nv_bfloat16* w1Lo = (__nv_bfloat16*)sym(g_w1Lo);
    __nv_bfloat16* w2Hi = (__nv_bfloat16*)sym(g_w2Hi); __nv_bfloat16* w2Lo = (__nv_bfloat16*)sym(g_w2Lo);
    __nv_bfloat16* w3Hi = (__nv_bfloat16*)sym(g_w3Hi); __nv_bfloat16* w3Lo = (__nv_bfloat16*)sym(g_w3Lo);
    __nv_bfloat16* w4Hi = (__nv_bfloat16*)sym(g_w4Hi); __nv_bfloat16* w4Lo = (__nv_bfloat16*)sym(g_w4Lo);
    __nv_bfloat16* w5Hi = (__nv_bfloat16*)sym(g_w5Hi); __nv_bfloat16* w5Lo = (__nv_bfloat16*)sym(g_w5Lo);
    __nv_bfloat16* aHi = (__nv_bfloat16*)sym(g_actAHi); __nv_bfloat16* aLo = (__nv_bfloat16*)sym(g_actALo);
    __nv_bfloat16* bHi = (__nv_bfloat16*)sym(g_actBHi); __nv_bfloat16* bLo = (__nv_bfloat16*)sym(g_actBLo);

    cudaFuncSetAttribute(gemm_bf16x3<0>, cudaFuncAttributeMaxDynamicSharedMemorySize, SMEM_TOTAL);
    cudaFuncSetAttribute(gemm_bf16x3<2>, cudaFuncAttributeMaxDynamicSharedMemorySize, SMEM_TOTAL);

    dim3 blk(GEMM_THREADS);

    // #1 concat, #2 w1, #3 w2, #4 w3  (prepack needed before L1-L3)
    concat_split_kernel<<<(B_ROWS * 192 + 255) / 256, 256>>>(state, pref, xHi, xLo);
    {
        int t1 = 2304 * 192;
        split_pad_bf16<<<(t1 + 255) / 256, 256>>>(w1, w1Hi, w1Lo, 2112, 132, 192, t1);
    }
    pad_rows_bf16pair<<<4352, 256>>>(w2, w2Hi, w2Lo, 4224, 2112);
    pad_rows_bf16pair<<<8448, 256>>>(w3, w3Hi, w3Lo, 8448, 4224);

    // #5 L1, #6 L2  (ncu -s 5 -c 1 captures this one)
    gemm_bf16x3<0><<<dim3(2304 / NT, B_ROWS / MT), blk, SMEM_TOTAL>>>(
        xHi, xLo, w1Hi, w1Lo, b1, aHi, aLo, nullptr, 2112, 192, 1);
    gemm_bf16x3<0><<<dim3(4352 / NT, B_ROWS / MT), blk, SMEM_TOTAL>>>(
        aHi, aLo, w2Hi, w2Lo, b2, bHi, bLo, nullptr, 4224, 2112, 1);

    // #7 w4, #8 L3, #9 L4
    pad_rows_bf16pair<<<4352, 256>>>(w4, w4Hi, w4Lo, 4224, 8448);
    gemm_bf16x3<0><<<dim3(8448 / NT, B_ROWS / MT), blk, SMEM_TOTAL>>>(
        bHi, bLo, w3Hi, w3Lo, b3, aHi, aLo, nullptr, 8448, 4224, 1);
    gemm_bf16x3<0><<<dim3(4352 / NT, B_ROWS / MT), blk, SMEM_TOTAL>>>(
        aHi, aLo, w4Hi, w4Lo, b4, bHi, bLo, nullptr, 4224, 8448, 1);

    // #10 w5, #11 L5, #12 envelope
    pad_rows_bf16pair<<<256, 256>>>(wq, w5Hi, w5Lo, 64, 4224);
    gemm_bf16x3<2><<<dim3(256 / NT, B_ROWS / MT), blk, SMEM_TOTAL>>>(
        bHi, bLo, w5Hi, w5Lo, bq, nullptr, nullptr, q, 64, 4224, 0);

    envelope_kernel<<<(B_ROWS + 255) / 256, 256>>>(q, pref, hq);
}

// round 7
// speedup vs baseline: 1.0640x; 1.0487x over previous
#include <cuda_runtime.h>
#include <cuda_bf16.h>
#include <cstdint>

// ============================================================================
// Problem constants
// ============================================================================
#define B_ROWS 8192

// L1: 132(Kpad192) -> 2112   grid 9  (8 full + tail64)
// L2: 2112         -> 4224   grid 17 (16 full + tail128)
// L3: 4224         -> 8448   grid 33 (all full)
// L4: 8448         -> 4224   grid 17 (16 full + tail128)
// L5: 4224         -> 64     grid 1  (tail64)

#define MT 128
#define NT 256
#define KC 64
#define GEMM_THREADS 256

#define STG_A_HI 0
#define STG_A_LO 16384
#define STG_W_HI 32768
#define STG_W_LO 65536
#define STAGE_BYTES 98304          // 96 KB
#define SMEM_TOTAL (2 * STAGE_BYTES)

// ============================================================================
// Scratch (__device__ globals; no cudaMalloc allowed)
// ============================================================================
__device__ __nv_bfloat16 g_xHi[B_ROWS * 192];
__device__ __nv_bfloat16 g_xLo[B_ROWS * 192];

__device__ __nv_bfloat16 g_w1Hi[2112 * 192],           g_w1Lo[2112 * 192];
__device__ __nv_bfloat16 g_w2Hi[(size_t)4224 * 2112],  g_w2Lo[(size_t)4224 * 2112];
__device__ __nv_bfloat16 g_w3Hi[(size_t)8448 * 4224],  g_w3Lo[(size_t)8448 * 4224];
__device__ __nv_bfloat16 g_w4Hi[(size_t)4224 * 8448],  g_w4Lo[(size_t)4224 * 8448];
__device__ __nv_bfloat16 g_w5Hi[64 * 4224],            g_w5Lo[64 * 4224];

__device__ __nv_bfloat16 g_actAHi[(size_t)B_ROWS * 8448], g_actALo[(size_t)B_ROWS * 8448];
__device__ __nv_bfloat16 g_actBHi[(size_t)B_ROWS * 4224], g_actBLo[(size_t)B_ROWS * 4224];

// ============================================================================
// PTX helpers
// ============================================================================
__device__ __forceinline__ uint32_t smem_u32(const void* p) {
    uint32_t a;
    asm("{ .reg .u64 t; cvta.to.shared.u64 t, %1; cvt.u32.u64 %0, t; }"
        : "=r"(a) : "l"(p));
    return a;
}

#define CP_ASYNC16(dst, src) \
    asm volatile("cp.async.cg.shared.global [%0], [%1], 16;" :: "r"(dst), "l"(src))

#define CP_COMMIT() asm volatile("cp.async.commit_group;" ::: "memory")
#define CP_WAIT(n)  asm volatile("cp.async.wait_group %0;" :: "n"(n) : "memory")

#define LDSM4(r, addr) \
    asm volatile("ldmatrix.sync.aligned.m8n8.x4.shared.b16 {%0,%1,%2,%3}, [%4];" \
                 : "=r"((r)[0]), "=r"((r)[1]), "=r"((r)[2]), "=r"((r)[3]) : "r"(addr))

#define MMA_BF16(d, a, b0, b1) \
    asm volatile("mma.sync.aligned.m16n8k16.row.col.f32.bf16.bf16.f32 " \
                 "{%0,%1,%2,%3},{%4,%5,%6,%7},{%8,%9},{%0,%1,%2,%3};" \
                 : "+f"((d)[0]), "+f"((d)[1]), "+f"((d)[2]), "+f"((d)[3]) \
                 : "r"((a)[0]), "r"((a)[1]), "r"((a)[2]), "r"((a)[3]), \
                   "r"(b0), "r"(b1))

__device__ __forceinline__ uint32_t swz(int r, int c) {
    return (uint32_t)(r * 128 + ((c ^ (r & 7)) << 4));
}

// ============================================================================
// GEMM body, templated on NPT (n p-tiles per warp: tile N width = NPT*64)
// and OUTFMT (0: bf16 hi/lo pair, 2: fp32)
// ============================================================================
template<int NPT, int OUTFMT>
__device__ __forceinline__ void gemm_body(
    char* smem,
    const __nv_bfloat16* __restrict__ aHi, const __nv_bfloat16* __restrict__ aLo,
    const __nv_bfloat16* __restrict__ wHi, const __nv_bfloat16* __restrict__ wLo,
    const float* __restrict__ bias,
    __nv_bfloat16* __restrict__ oHi, __nv_bfloat16* __restrict__ oLo,
    float* __restrict__ oF,
    int Nreal, int Kpad, int doRelu)
{
    const uint32_t sb = smem_u32(smem);
    const int tid  = threadIdx.x;
    const int wid  = tid >> 5;
    const int lane = tid & 31;
    const int m0 = blockIdx.y * MT;
    const int n0 = blockIdx.x * NT;
    const int nChunks = Kpad / KC;

    auto load_chunk = [&](int c, int stage) {
        const uint32_t base = sb + stage * STAGE_BYTES;
        const int k0 = c * KC;
        #pragma unroll
        for (int i = 0; i < 4; i++) {                    // A: 1024 x 16B
            int j = tid + i * GEMM_THREADS;
            int r = j >> 3, cc = j & 7;
            uint32_t d = base + swz(r, cc);
            size_t so = (size_t)(m0 + r) * Kpad + k0 + cc * 8;
            CP_ASYNC16(d + STG_A_HI, aHi + so);
            CP_ASYNC16(d + STG_A_LO, aLo + so);
        }
        #pragma unroll
        for (int i = 0; i < 2 * NPT; i++) {              // W: NPT*64 rows x 8 x 16B
            int j = tid + i * GEMM_THREADS;
            int r = j >> 3, cc = j & 7;
            uint32_t d = base + swz(r, cc);
            size_t so = (size_t)(n0 + r) * Kpad + k0 + cc * 8;
            CP_ASYNC16(d + STG_W_HI, wHi + so);
            CP_ASYNC16(d + STG_W_LO, wLo + so);
        }
    };

    float acc[4][2 * NPT][4];
    #pragma unroll
    for (int t = 0; t < 4; t++)
        #pragma unroll
        for (int nf = 0; nf < 2 * NPT; nf++)
            #pragma unroll
            for (int e = 0; e < 4; e++) acc[t][nf][e] = 0.0f;

    const int mBase = (wid & 1) * 64;
    const int nBase = (wid >> 1) * (NPT * 16);

    load_chunk(0, 0);
    CP_COMMIT();

    for (int c = 0; c < nChunks; c++) {
        if (c + 1 < nChunks) {
            load_chunk(c + 1, (c + 1) & 1);
            CP_COMMIT();
            CP_WAIT(1);
        } else {
            CP_WAIT(0);
        }
        __syncthreads();

        const uint32_t base = sb + (c & 1) * STAGE_BYTES;
        #pragma unroll
        for (int s = 0; s < 4; s++) {
            uint32_t aH[4][4], aL[4][4];
            #pragma unroll
            for (int t = 0; t < 4; t++) {
                int row = mBase + t * 16 + (lane & 15);
                int c16 = s * 2 + (lane >> 4);
                uint32_t ad = base + swz(row, c16);
                LDSM4(aH[t], ad + STG_A_HI);
                LDSM4(aL[t], ad + STG_A_LO);
            }
            #pragma unroll
            for (int p = 0; p < NPT; p++) {
                int g = lane >> 3;
                int row = nBase + p * 16 + (lane & 7) + ((g >> 1) << 3);
                int c16 = s * 2 + (g & 1);
                uint32_t wd = base + swz(row, c16);
                uint32_t bH[4], bL[4];
                LDSM4(bH, wd + STG_W_HI);
                LDSM4(bL, wd + STG_W_LO);
                #pragma unroll
                for (int t = 0; t < 4; t++) {
                    MMA_BF16(acc[t][2 * p],     aH[t], bH[0], bH[1]);
                    MMA_BF16(acc[t][2 * p + 1], aH[t], bH[2], bH[3]);
                }
                #pragma unroll
                for (int t = 0; t < 4; t++) {
                    MMA_BF16(acc[t][2 * p],     aL[t], bH[0], bH[1]);
                    MMA_BF16(acc[t][2 * p + 1], aL[t], bH[2], bH[3]);
                }
                #pragma unroll
                for (int t = 0; t < 4; t++) {
                    MMA_BF16(acc[t][2 * p],     aH[t], bL[0], bL[1]);
                    MMA_BF16(acc[t][2 * p + 1], aH[t], bL[2], bL[3]);
                }
            }
        }
        __syncthreads();
    }

    // ---------------- epilogue ---------------------------------------------
    const int mW = m0 + mBase;
    const int nW = n0 + nBase;
    #pragma unroll
    for (int t = 0; t < 4; t++) {
        #pragma unroll
        for (int nf = 0; nf < 2 * NPT; nf++) {
            int cc = nW + nf * 8 + ((lane & 3) << 1);
            if (cc >= Nreal) continue;
            int r0 = mW + t * 16 + (lane >> 2);
            int r1 = r0 + 8;
            float bv0 = bias[cc], bv1 = bias[cc + 1];
            float v00 = acc[t][nf][0] + bv0;
            float v01 = acc[t][nf][1] + bv1;
            float v10 = acc[t][nf][2] + bv0;
            float v11 = acc[t][nf][3] + bv1;
            if (doRelu) {
                v00 = fmaxf(v00, 0.f); v01 = fmaxf(v01, 0.f);
                v10 = fmaxf(v10, 0.f); v11 = fmaxf(v11, 0.f);
            }
            if constexpr (OUTFMT == 2) {
                *reinterpret_cast<float2*>(oF + (size_t)r0 * Nreal + cc) = make_float2(v00, v01);
                *reinterpret_cast<float2*>(oF + (size_t)r1 * Nreal + cc) = make_float2(v10, v11);
            } else {
                __nv_bfloat16 h00 = __float2bfloat16(v00), h01 = __float2bfloat16(v01);
                __nv_bfloat16 h10 = __float2bfloat16(v10), h11 = __float2bfloat16(v11);
                __nv_bfloat16 l00 = __float2bfloat16(v00 - __bfloat162float(h00));
                __nv_bfloat16 l01 = __float2bfloat16(v01 - __bfloat162float(h01));
                __nv_bfloat16 l10 = __float2bfloat16(v10 - __bfloat162float(h10));
                __nv_bfloat16 l11 = __float2bfloat16(v11 - __bfloat162float(h11));
                *reinterpret_cast<__nv_bfloat162*>(oHi + (size_t)r0 * Nreal + cc) = __nv_bfloat162(h00, h01);
                *reinterpret_cast<__nv_bfloat162*>(oHi + (size_t)r1 * Nreal + cc) = __nv_bfloat162(h10, h11);
                *reinterpret_cast<__nv_bfloat162*>(oLo + (size_t)r0 * Nreal + cc) = __nv_bfloat162(l00, l01);
                *reinterpret_cast<__nv_bfloat162*>(oLo + (size_t)r1 * Nreal + cc) = __nv_bfloat162(l10, l11);
            }
        }
    }
}

template<int OUTFMT>
__global__ void __launch_bounds__(GEMM_THREADS, 1)
gemm_bf16x3(const __nv_bfloat16* __restrict__ aHi, const __nv_bfloat16* __restrict__ aLo,
            const __nv_bfloat16* __restrict__ wHi, const __nv_bfloat16* __restrict__ wLo,
            const float* __restrict__ bias,
            __nv_bfloat16* __restrict__ oHi, __nv_bfloat16* __restrict__ oLo,
            float* __restrict__ oF,
            int Nreal, int Kpad, int doRelu)
{
    extern __shared__ char smem[];
    const int rem = Nreal - blockIdx.x * NT;   // uniform across block
    if (rem >= 256)
        gemm_body<4, OUTFMT>(smem, aHi, aLo, wHi, wLo, bias, oHi, oLo, oF, Nreal, Kpad, doRelu);
    else if (rem >= 128)
        gemm_body<2, OUTFMT>(smem, aHi, aLo, wHi, wLo, bias, oHi, oLo, oF, Nreal, Kpad, doRelu);
    else
        gemm_body<1, OUTFMT>(smem, aHi, aLo, wHi, wLo, bias, oHi, oLo, oF, Nreal, Kpad, doRelu);
}

// ============================================================================
// Prepack kernels
// ============================================================================
// fused: concat-split (blocks [0, 6144)) + w1 split-pad-K (blocks [6144, 7728))
#define CONCAT_BLOCKS 6144
#define W1_BLOCKS 1584
__global__ void prep_fused(const float* __restrict__ state,
                           const float* __restrict__ pref,
                           __nv_bfloat16* __restrict__ xHi, __nv_bfloat16* __restrict__ xLo,
                           const float* __restrict__ w1,
                           __nv_bfloat16* __restrict__ w1Hi, __nv_bfloat16* __restrict__ w1Lo)
{
    if (blockIdx.x < CONCAT_BLOCKS) {
        int idx = blockIdx.x * blockDim.x + threadIdx.x;   // < 8192*192
        int b = idx / 192, c = idx - b * 192;
        float v = 0.0f;
        if (c < 128)      v = state[b * 128 + c];
        else if (c < 132) v = pref[b * 4 + (c - 128)];
        __nv_bfloat16 h = __float2bfloat16(v);
        xHi[idx] = h;
        xLo[idx] = __float2bfloat16(v - __bfloat162float(h));
    } else {
        int idx = (blockIdx.x - CONCAT_BLOCKS) * blockDim.x + threadIdx.x;  // < 2112*192
        int n = idx / 192, k = idx - n * 192;
        float v = (k < 132) ? w1[n * 132 + k] : 0.0f;
        __nv_bfloat16 h = __float2bfloat16(v);
        w1Hi[idx] = h;
        w1Lo[idx] = __float2bfloat16(v - __bfloat162float(h));
    }
}

__global__ void pad_rows_bf16pair(const float* __restrict__ W,
                                  __nv_bfloat16* __restrict__ hi,
                                  __nv_bfloat16* __restrict__ lo,
                                  int K)
{
    int n = blockIdx.x;
    const float4* src = reinterpret_cast<const float4*>(W + (size_t)n * K);
    uint2* dhi = reinterpret_cast<uint2*>(hi + (size_t)n * K);
    uint2* dlo = reinterpret_cast<uint2*>(lo + (size_t)n * K);
    int nv = K >> 2;
    for (int i = threadIdx.x; i < nv; i += blockDim.x) {
        float4 v = src[i];
        __nv_bfloat16 h0 = __float2bfloat16(v.x), h1 = __float2bfloat16(v.y);
        __nv_bfloat16 h2 = __float2bfloat16(v.z), h3 = __float2bfloat16(v.w);
        uint2 uh, ul;
        uh.x = (uint32_t)__bfloat16_as_ushort(h0) | ((uint32_t)__bfloat16_as_ushort(h1) << 16);
        uh.y = (uint32_t)__bfloat16_as_ushort(h2) | ((uint32_t)__bfloat16_as_ushort(h3) << 16);
        __nv_bfloat16 l0 = __float2bfloat16(v.x - __bfloat162float(h0));
        __nv_bfloat16 l1 = __float2bfloat16(v.y - __bfloat162float(h1));
        __nv_bfloat16 l2 = __float2bfloat16(v.z - __bfloat162float(h2));
        __nv_bfloat16 l3 = __float2bfloat16(v.w - __bfloat162float(h3));
        ul.x = (uint32_t)__bfloat16_as_ushort(l0) | ((uint32_t)__bfloat16_as_ushort(l1) << 16);
        ul.y = (uint32_t)__bfloat16_as_ushort(l2) | ((uint32_t)__bfloat16_as_ushort(l3) << 16);
        dhi[i] = uh;
        dlo[i] = ul;
    }
}

// ============================================================================
// envelope
// ============================================================================
__global__ void envelope_kernel(const float* __restrict__ q,
                                const float* __restrict__ pref,
                                float* __restrict__ hq)
{
    int b = blockIdx.x * blockDim.x + threadIdx.x;
    if (b >= B_ROWS) return;
    float p0 = pref[b * 4 + 0], p1 = pref[b * 4 + 1];
    float p2 = pref[b * 4 + 2], p3 = pref[b * 4 + 3];
    const float* qb = q + (size_t)b * 64;
    float best = -3.402823466e+38f;
    int ba = 0;
    #pragma unroll
    for (int a = 0; a < 16; a++) {
        float ip = qb[a * 4 + 0] * p0 + qb[a * 4 + 1] * p1
                 + qb[a * 4 + 2] * p2 + qb[a * 4 + 3] * p3;
        if (ip > best) { best = ip; ba = a; }
    }
    hq[b * 4 + 0] = qb[ba * 4 + 0];
    hq[b * 4 + 1] = qb[ba * 4 + 1];
    hq[b * 4 + 2] = qb[ba * 4 + 2];
    hq[b * 4 + 3] = qb[ba * 4 + 3];
}

// ============================================================================
// launch — launch #4 (ncu capture slot) = L2's GEMM
// ============================================================================
static inline void* sym(const void* s) { void* p; cudaGetSymbolAddress(&p, s); return p; }

extern "C" void kernel_launch(void* const* d_in, const int* in_sizes, int n_in,
                              void* d_out, int out_size)
{
    const float* state = (const float*)d_in[0];
    const float* pref  = (const float*)d_in[1];
    const float* w1 = (const float*)d_in[2];  const float* b1 = (const float*)d_in[3];
    const float* w2 = (const float*)d_in[4];  const float* b2 = (const float*)d_in[5];
    const float* w3 = (const float*)d_in[6];  const float* b3 = (const float*)d_in[7];
    const float* w4 = (const float*)d_in[8];  const float* b4 = (const float*)d_in[9];
    const float* wq = (const float*)d_in[10]; const float* bq = (const float*)d_in[11];

    float* out = (float*)d_out;
    float* hq = out;                       // [8192, 4]
    float* q  = out + (size_t)B_ROWS * 4;  // [8192, 64]

    __nv_bfloat16* xHi = (__nv_bfloat16*)sym(g_xHi);
    __nv_bfloat16* xLo = (__nv_bfloat16*)sym(g_xLo);
    __nv_bfloat16* w1Hi = (__nv_bfloat16*)sym(g_w1Hi); __nv_bfloat16* w1Lo = (__nv_bfloat16*)sym(g_w1Lo);
    __nv_bfloat16* w2Hi = (__nv_bfloat16*)sym(g_w2Hi); __nv_bfloat16* w2Lo = (__nv_bfloat16*)sym(g_w2Lo);
    __nv_bfloat16* w3Hi = (__nv_bfloat16*)sym(g_w3Hi); __nv_bfloat16* w3Lo = (__nv_bfloat16*)sym(g_w3Lo);
    __nv_bfloat16* w4Hi = (__nv_bfloat16*)sym(g_w4Hi); __nv_bfloat16* w4Lo = (__nv_bfloat16*)sym(g_w4Lo);
    __nv_bfloat16* w5Hi = (__nv_bfloat16*)sym(g_w5Hi); __nv_bfloat16* w5Lo = (__nv_bfloat16*)sym(g_w5Lo);
    __nv_bfloat16* aHi = (__nv_bfloat16*)sym(g_actAHi); __nv_bfloat16* aLo = (__nv_bfloat16*)sym(g_actALo);
    __nv_bfloat16* bHi = (__nv_bfloat16*)sym(g_actBHi); __nv_bfloat16* bLo = (__nv_bfloat16*)sym(g_actBLo);

    cudaFuncSetAttribute(gemm_bf16x3<0>, cudaFuncAttributeMaxDynamicSharedMemorySize, SMEM_TOTAL);
    cudaFuncSetAttribute(gemm_bf16x3<2>, cudaFuncAttributeMaxDynamicSharedMemorySize, SMEM_TOTAL);

    dim3 blk(GEMM_THREADS);

    // #1 fused concat + w1 prepack
    prep_fused<<<CONCAT_BLOCKS + W1_BLOCKS, 256>>>(state, pref, xHi, xLo, w1, w1Hi, w1Lo);
    // #2 w2 prepack
    pad_rows_bf16pair<<<4224, 256>>>(w2, w2Hi, w2Lo, 2112);
    // #3 L1: [8192,192] x [2112,192] -> actA (2112)
    gemm_bf16x3<0><<<dim3(9, B_ROWS / MT), blk, SMEM_TOTAL>>>(
        xHi, xLo, w1Hi, w1Lo, b1, aHi, aLo, nullptr, 2112, 192, 1);
    // #4 L2: [8192,2112] x [4224,2112] -> actB (4224)   <-- ncu capture slot
    gemm_bf16x3<0><<<dim3(17, B_ROWS / MT), blk, SMEM_TOTAL>>>(
        aHi, aLo, w2Hi, w2Lo, b2, bHi, bLo, nullptr, 4224, 2112, 1);
    // #5 w3 prepack
    pad_rows_bf16pair<<<8448, 256>>>(w3, w3Hi, w3Lo, 4224);
    // #6 L3: [8192,4224] x [8448,4224] -> actA (8448)
    gemm_bf16x3<0><<<dim3(33, B_ROWS / MT), blk, SMEM_TOTAL>>>(
        bHi, bLo, w3Hi, w3Lo, b3, aHi, aLo, nullptr, 8448, 4224, 1);
    // #7 w4 prepack
    pad_rows_bf16pair<<<4224, 256>>>(w4, w4Hi, w4Lo, 8448);
    // #8 L4: [8192,8448] x [4224,8448] -> actB (4224)
    gemm_bf16x3<0><<<dim3(17, B_ROWS / MT), blk, SMEM_TOTAL>>>(
        aHi, aLo, w4Hi, w4Lo, b4, bHi, bLo, nullptr, 4224, 8448, 1);
    // #9 w5 prepack
    pad_rows_bf16pair<<<64, 256>>>(wq, w5Hi, w5Lo, 4224);
    // #10 L5: [8192,4224] x [64,4224] -> q fp32 (64)
    gemm_bf16x3<2><<<dim3(1, B_ROWS / MT), blk, SMEM_TOTAL>>>(
        bHi, bLo, w5Hi, w5Lo, bq, nullptr, nullptr, q, 64, 4224, 0);
    // #11 envelope
    envelope_kernel<<<(B_ROWS + 255) / 256, 256>>>(q, pref, hq);
}